// round 13
// baseline (speedup 1.0000x reference)
#include <cuda_runtime.h>
#include <cuda_fp16.h>
#include <stdint.h>

// ---------------------------------------------------------------------------
// Attention3D on fp16 tensor cores (mma.sync m16n8k16, fp32 accumulate).
//   0) prep (2 kernels): x -> fp16; weights -> fp16 k-pair-interleaved
//   1) QKV GEMM -> Q/K/V fp16 natural [hb][n][c]
//   2) flash attention Br=128 Bc=64: rel-pos tables computed in prologue
//      from smem Q (no global round-trip); P in registers; V via ldsm.trans
//   3) proj GEMM -> fp32 d_out
// ---------------------------------------------------------------------------

#define NHB  24
#define NSEQ 2048
#define HD   64
#define CDIM 768

__device__ __half  g_q[NHB * NSEQ * HD];
__device__ __half  g_k[NHB * NSEQ * HD];
__device__ __half  g_v[NHB * NSEQ * HD];        // natural [hb][n][c]
__device__ __half  g_attnout[4096 * CDIM];
__device__ __half  g_xr[4096 * CDIM];
__device__ __half2 g_qkvw[384 * 2304];          // [k/2][n] pairs
__device__ __half2 g_projw[384 * 768];

// --- helpers ---------------------------------------------------------------
__device__ __forceinline__ void cpa16(void* dst, const void* src) {
    uint32_t d = (uint32_t)__cvta_generic_to_shared(dst);
    asm volatile("cp.async.cg.shared.global [%0], [%1], 16;" :: "r"(d), "l"(src));
}
__device__ __forceinline__ void cp_commit() {
    asm volatile("cp.async.commit_group;");
}
__device__ __forceinline__ void cp_wait0() {
    asm volatile("cp.async.wait_group 0;");
}
__device__ __forceinline__ void ldsm4(uint32_t r[4], const void* p) {
    uint32_t a = (uint32_t)__cvta_generic_to_shared(p);
    asm volatile("ldmatrix.sync.aligned.m8n8.x4.shared.b16 {%0,%1,%2,%3}, [%4];"
                 : "=r"(r[0]), "=r"(r[1]), "=r"(r[2]), "=r"(r[3]) : "r"(a));
}
__device__ __forceinline__ void ldsm4t(uint32_t r[4], const void* p) {
    uint32_t a = (uint32_t)__cvta_generic_to_shared(p);
    asm volatile("ldmatrix.sync.aligned.m8n8.x4.trans.shared.b16 {%0,%1,%2,%3}, [%4];"
                 : "=r"(r[0]), "=r"(r[1]), "=r"(r[2]), "=r"(r[3]) : "r"(a));
}
__device__ __forceinline__ void mma16(float d[4], const uint32_t a[4],
                                      uint32_t b0, uint32_t b1) {
    asm volatile(
        "mma.sync.aligned.m16n8k16.row.col.f32.f16.f16.f32 "
        "{%0,%1,%2,%3}, {%4,%5,%6,%7}, {%8,%9}, {%0,%1,%2,%3};"
        : "+f"(d[0]), "+f"(d[1]), "+f"(d[2]), "+f"(d[3])
        : "r"(a[0]), "r"(a[1]), "r"(a[2]), "r"(a[3]), "r"(b0), "r"(b1));
}
__device__ __forceinline__ uint32_t packh2(float lo, float hi) {
    __half2 h = __floats2half2_rn(lo, hi);
    return *(uint32_t*)&h;
}

// ---------------------------------------------------------------------------
// Prep kernels (2 so that flash is launch #4 -> ncu capture target)
// ---------------------------------------------------------------------------
__global__ void __launch_bounds__(256) prep_x(const float* __restrict__ x)
{
    const int stride = gridDim.x * 256;
    for (int f = blockIdx.x * 256 + threadIdx.x; f < (4096 * CDIM) / 4; f += stride) {
        float4 v = *(const float4*)&x[f * 4];
        *(uint2*)&g_xr[f * 4] = make_uint2(packh2(v.x, v.y), packh2(v.z, v.w));
    }
}
__global__ void __launch_bounds__(256) prep_w(const float* __restrict__ qw,
                                              const float* __restrict__ pw)
{
    const int stride = gridDim.x * 256;
    const int t = blockIdx.x * 256 + threadIdx.x;
    for (int i = t; i < 384 * 2304; i += stride) {
        const int k2 = i / 2304, n = i - k2 * 2304;
        g_qkvw[i] = __floats2half2_rn(qw[(2 * k2) * 2304 + n],
                                      qw[(2 * k2 + 1) * 2304 + n]);
    }
    for (int i = t; i < 384 * 768; i += stride) {
        const int k2 = i / 768, n = i - k2 * 768;
        g_projw[i] = __floats2half2_rn(pw[(2 * k2) * 768 + n],
                                       pw[(2 * k2 + 1) * 768 + n]);
    }
}

// ---------------------------------------------------------------------------
// fp16 GEMM: 128x128 tile, k-step 32 (24 iters), 2-stage cp.async.
// ---------------------------------------------------------------------------
template <int MODE>
__global__ void __launch_bounds__(256) mm_fp16(
    const float* __restrict__ bias, float* __restrict__ out)
{
    constexpr int N = (MODE == 0) ? 2304 : 768;
    __shared__ __half   As[2][128 * 40];
    __shared__ uint32_t Bs[2][16 * 136];
    const int tid = threadIdx.x, lane = tid & 31, w = tid >> 5;
    const int wm = w >> 1, wn = w & 1;
    const int bm = blockIdx.x * 128, bn = blockIdx.y * 128;
    const __half* Ap = (MODE == 0) ? g_xr : g_attnout;
    const uint32_t* Wp = (const uint32_t*)((MODE == 0) ? g_qkvw : g_projw);

    float c[2][8][4];
#pragma unroll
    for (int i = 0; i < 2; i++)
#pragma unroll
        for (int j = 0; j < 8; j++)
#pragma unroll
            for (int k = 0; k < 4; k++) c[i][j][k] = 0.f;

    auto stage = [&](int k0, int buf) {
        const int k20 = k0 >> 1;
#pragma unroll
        for (int it = 0; it < 2; it++) {
            const int i = tid + it * 256;
            const int r = i >> 2, c8 = (i & 3) << 3;
            cpa16(&As[buf][r * 40 + c8], &Ap[(bm + r) * 768 + k0 + c8]);
        }
#pragma unroll
        for (int it = 0; it < 2; it++) {
            const int i = tid + it * 256;
            const int kk = i >> 5, n4 = (i & 31) << 2;
            cpa16(&Bs[buf][kk * 136 + n4], &Wp[(k20 + kk) * N + bn + n4]);
        }
    };

    stage(0, 0); cp_commit();

    int buf = 0;
    for (int k0 = 0; k0 < 768; k0 += 32, buf ^= 1) {
        cp_wait0();
        __syncthreads();
        if (k0 + 32 < 768) { stage(k0 + 32, buf ^ 1); cp_commit(); }

        const uint32_t* bp = Bs[buf];
#pragma unroll
        for (int ks = 0; ks < 2; ks++) {
            uint32_t a0[4], a1[4];
            ldsm4(a0, &As[buf][(wm * 32 + ((lane >> 3) & 1) * 8 + (lane & 7)) * 40
                               + ks * 16 + (lane >> 4) * 8]);
            ldsm4(a1, &As[buf][(wm * 32 + 16 + ((lane >> 3) & 1) * 8 + (lane & 7)) * 40
                               + ks * 16 + (lane >> 4) * 8]);
#pragma unroll
            for (int nt = 0; nt < 8; nt++) {
                const int ncol = wn * 64 + nt * 8 + (lane >> 2);
                uint32_t b0 = bp[(ks * 8 + (lane & 3)) * 136 + ncol];
                uint32_t b1 = bp[(ks * 8 + 4 + (lane & 3)) * 136 + ncol];
                mma16(c[0][nt], a0, b0, b1);
                mma16(c[1][nt], a1, b0, b1);
            }
        }
        __syncthreads();
    }

    if (MODE == 0) {
        const int hc = bn + wn * 64;
        const int which = hc / 768;
        const int head = (hc % 768) >> 6;
        __half* dst = (which == 0) ? g_q : (which == 1) ? g_k : g_v;
#pragma unroll
        for (int mt = 0; mt < 2; mt++)
#pragma unroll
            for (int nt = 0; nt < 8; nt++) {
                const int ccol = nt * 8 + ((lane & 3) << 1);
                const float b0v = bias[hc + ccol];
                const float b1v = bias[hc + ccol + 1];
#pragma unroll
                for (int h = 0; h < 2; h++) {
                    const int row = bm + wm * 32 + mt * 16 + (lane >> 2) + 8 * h;
                    const int b_ = row >> 11, n = row & 2047;
                    const int hb = b_ * 12 + head;
                    *(__half2*)&dst[((size_t)(hb * NSEQ + n) << 6) + ccol] =
                        __floats2half2_rn(c[mt][nt][2 * h] + b0v,
                                          c[mt][nt][2 * h + 1] + b1v);
                }
            }
    } else {
#pragma unroll
        for (int mt = 0; mt < 2; mt++)
#pragma unroll
            for (int nt = 0; nt < 8; nt++) {
                const int col = bn + wn * 64 + nt * 8 + ((lane & 3) << 1);
                const float b0v = bias[col], b1v = bias[col + 1];
#pragma unroll
                for (int h = 0; h < 2; h++) {
                    const int row = bm + wm * 32 + mt * 16 + (lane >> 2) + 8 * h;
                    *(float2*)&out[row * 768 + col] =
                        make_float2(c[mt][nt][2 * h] + b0v, c[mt][nt][2 * h + 1] + b1v);
                }
            }
    }
}

// ---------------------------------------------------------------------------
// Flash attention fp16: Br=128, Bc=64, 8 warps, 32 iters.
// Rel-pos tables computed in prologue from smem Q (vectorized dot products);
// P in registers (C-frag == A-frag); V natural via ldmatrix.trans.
// smem: Qh 128x72h=18432 | K 2x64x72h=18432 | V 2x64x72h=18432 |
//       rDt 4096 | rHt 8192 | rWt 8192  = 75776 B   (2 CTAs/SM)
// ---------------------------------------------------------------------------
#define FL_BYTES 75776

__global__ void __launch_bounds__(256, 2) flash_kernel(
    const float* __restrict__ rpd, const float* __restrict__ rph,
    const float* __restrict__ rpw)
{
    extern __shared__ char smc[];
    __half* Qh = (__half*)smc;                    // pitch 72
    __half* Kh = (__half*)(smc + 18432);
    __half* Vh = (__half*)(smc + 36864);
    float* rDt = (float*)(smc + 55296);
    float* rHt = (float*)(smc + 59392);
    float* rWt = (float*)(smc + 67584);

    const int tid = threadIdx.x, lane = tid & 31, w = tid >> 5;
    const int hb = blockIdx.y;
    const int qbase = blockIdx.x * 128;
    const float scale = 0.125f;

    auto stageKV = [&](int kt, int buf) {
        const __half* Kg = &g_k[(size_t)(hb * NSEQ + kt * 64) * HD];
        const __half* Vg = &g_v[(size_t)(hb * NSEQ + kt * 64) * HD];
        __half* Kb = Kh + buf * 4608;
        __half* Vb = Vh + buf * 4608;
#pragma unroll
        for (int it = 0; it < 2; it++) {
            const int i = tid + it * 256;
            const int r = i >> 3, c8 = (i & 7) << 3;
            cpa16(&Kb[r * 72 + c8], &Kg[r * 64 + c8]);
            cpa16(&Vb[r * 72 + c8], &Vg[r * 64 + c8]);
        }
    };

    stageKV(0, 0); cp_commit();

    // --- stage Q ---
    const __half* Qg = &g_q[(size_t)(hb * NSEQ + qbase) * HD];
#pragma unroll
    for (int it = 0; it < 4; it++) {
        const int i = tid + it * 256;
        const int r = i >> 3, c8 = (i & 7) << 3;
        *(uint4*)&Qh[r * 72 + c8] = *(const uint4*)&Qg[r * 64 + c8];
    }
    __syncthreads();   // Q visible for prologue dots

    // --- rel-pos tables from smem Q (vectorized: half2 q, float4 table) ---
    for (int i = tid; i < 128 * 40; i += 256) {
        const int row = i / 40, j = i - row * 40;
        const int n = qbase + row;
        const int d = n >> 8, h = (n >> 4) & 15, wq = n & 15;
        const float* trow;
        float* dst;
        if (j < 8)       { trow = &rpd[(d - j + 7) * HD];        dst = &rDt[j * 128 + row]; }
        else if (j < 24) { const int kh = j - 8;  trow = &rph[(h - kh + 15) * HD];  dst = &rHt[kh * 128 + row]; }
        else             { const int kw = j - 24; trow = &rpw[(wq - kw + 15) * HD]; dst = &rWt[kw * 128 + row]; }
        const __half2* q2 = (const __half2*)&Qh[row * 72];
        const float4* t4 = (const float4*)trow;
        float s = 0.f;
#pragma unroll
        for (int c = 0; c < 16; c++) {
            float4 t = t4[c];
            float2 qa = __half22float2(q2[2 * c]);
            float2 qb = __half22float2(q2[2 * c + 1]);
            s += qa.x * t.x + qa.y * t.y + qb.x * t.z + qb.y * t.w;
        }
        *dst = s;
    }
    __syncthreads();   // tables visible

    // --- hoist Q A-fragments + per-thread rW values ---
    uint32_t aq[4][4];
#pragma unroll
    for (int ksp = 0; ksp < 4; ksp++)
        ldsm4(aq[ksp], &Qh[(w * 16 + ((lane >> 3) & 1) * 8 + (lane & 7)) * 72
                           + ksp * 16 + (lane >> 4) * 8]);
    int rq[2];
    rq[0] = w * 16 + (lane >> 2);
    rq[1] = rq[0] + 8;
    float rw[2][2][2];
#pragma unroll
    for (int p = 0; p < 2; p++)
#pragma unroll
        for (int j2 = 0; j2 < 2; j2++)
#pragma unroll
            for (int h = 0; h < 2; h++)
                rw[p][j2][h] = rWt[(8 * p + 2 * (lane & 3) + j2) * 128 + rq[h]];

    float m[2] = {-1e30f, -1e30f}, l[2] = {0.f, 0.f};
    float o[8][4];
#pragma unroll
    for (int i = 0; i < 8; i++)
#pragma unroll
        for (int j = 0; j < 4; j++) o[i][j] = 0.f;

    int buf = 0;
    for (int kt = 0; kt < 32; kt++, buf ^= 1) {
        cp_wait0();
        __syncthreads();
        if (kt + 1 < 32) { stageKV(kt + 1, buf ^ 1); cp_commit(); }
        const __half* Kb = Kh + buf * 4608;
        const __half* Vb = Vh + buf * 4608;

        // --- S = Q K^T ---
        float s[8][4];
#pragma unroll
        for (int i = 0; i < 8; i++)
#pragma unroll
            for (int j = 0; j < 4; j++) s[i][j] = 0.f;
#pragma unroll
        for (int kp = 0; kp < 2; kp++) {
#pragma unroll
            for (int nt = 0; nt < 8; nt++) {
                uint32_t k4[4];
                ldsm4(k4, &Kb[(nt * 8 + (lane & 7)) * 72 + kp * 32 + (lane >> 3) * 8]);
                mma16(s[nt], aq[2 * kp], k4[0], k4[1]);
                mma16(s[nt], aq[2 * kp + 1], k4[2], k4[3]);
            }
        }

        // --- scale + bias ---
        const int kd = kt >> 2;
        float bh[4][2];
#pragma unroll
        for (int g = 0; g < 4; g++)
#pragma unroll
            for (int h = 0; h < 2; h++)
                bh[g][h] = rDt[kd * 128 + rq[h]]
                         + rHt[((kt & 3) * 4 + g) * 128 + rq[h]];
#pragma unroll
        for (int nt = 0; nt < 8; nt++)
#pragma unroll
            for (int h = 0; h < 2; h++)
#pragma unroll
                for (int j2 = 0; j2 < 2; j2++)
                    s[nt][2 * h + j2] = fmaf(s[nt][2 * h + j2], scale,
                                             bh[nt >> 1][h] + rw[nt & 1][j2][h]);

        // --- online softmax ---
#pragma unroll
        for (int h = 0; h < 2; h++) {
            float rmax = s[0][2 * h];
#pragma unroll
            for (int nt = 0; nt < 8; nt++) {
                rmax = fmaxf(rmax, s[nt][2 * h]);
                rmax = fmaxf(rmax, s[nt][2 * h + 1]);
            }
            rmax = fmaxf(rmax, __shfl_xor_sync(0xffffffffu, rmax, 1));
            rmax = fmaxf(rmax, __shfl_xor_sync(0xffffffffu, rmax, 2));
            const float mn = fmaxf(m[h], rmax);
            const float corr = __expf(m[h] - mn);
            m[h] = mn;
            float rs = 0.f;
#pragma unroll
            for (int nt = 0; nt < 8; nt++) {
                s[nt][2 * h]     = __expf(s[nt][2 * h] - mn);
                s[nt][2 * h + 1] = __expf(s[nt][2 * h + 1] - mn);
                rs += s[nt][2 * h] + s[nt][2 * h + 1];
            }
            rs += __shfl_xor_sync(0xffffffffu, rs, 1);
            rs += __shfl_xor_sync(0xffffffffu, rs, 2);
            l[h] = l[h] * corr + rs;
#pragma unroll
            for (int nt = 0; nt < 8; nt++) {
                o[nt][2 * h] *= corr;
                o[nt][2 * h + 1] *= corr;
            }
        }

        // --- pack P as A-fragments (C-frag layout == A-frag layout) ---
        uint32_t pa[4][4];
#pragma unroll
        for (int kc = 0; kc < 4; kc++) {
            pa[kc][0] = packh2(s[2 * kc][0],     s[2 * kc][1]);
            pa[kc][1] = packh2(s[2 * kc][2],     s[2 * kc][3]);
            pa[kc][2] = packh2(s[2 * kc + 1][0], s[2 * kc + 1][1]);
            pa[kc][3] = packh2(s[2 * kc + 1][2], s[2 * kc + 1][3]);
        }

        // --- O += P V : V natural [key][c], B-frags via ldmatrix.trans ---
#pragma unroll
        for (int kp = 0; kp < 4; kp++) {        // 16 keys each
#pragma unroll
            for (int cb = 0; cb < 4; cb++) {    // 16 c-cols each
                uint32_t v4[4];
                ldsm4t(v4, &Vb[(kp * 16 + ((lane >> 3) & 1) * 8 + (lane & 7)) * 72
                               + cb * 16 + (lane >> 4) * 8]);
                mma16(o[2 * cb],     pa[kp], v4[0], v4[1]);
                mma16(o[2 * cb + 1], pa[kp], v4[2], v4[3]);
            }
        }
    }

    // --- finalize: fp16 attnout (proj A operand) ---
    const int b = hb / 12, head = hb % 12;
#pragma unroll
    for (int h = 0; h < 2; h++) {
        const float inv = 1.0f / l[h];
        const int qg = qbase + rq[h];
        __half* orow = &g_attnout[(size_t)(b * NSEQ + qg) * CDIM + head * 64];
#pragma unroll
        for (int nt = 0; nt < 8; nt++)
            *(__half2*)&orow[nt * 8 + 2 * (lane & 3)] =
                __floats2half2_rn(o[nt][2 * h] * inv, o[nt][2 * h + 1] * inv);
    }
}

// ---------------------------------------------------------------------------
extern "C" void kernel_launch(void* const* d_in, const int* in_sizes, int n_in,
                              void* d_out, int out_size)
{
    const float* x      = (const float*)d_in[0];
    const float* qkv_w  = (const float*)d_in[1];
    const float* qkv_b  = (const float*)d_in[2];
    const float* proj_w = (const float*)d_in[3];
    const float* proj_b = (const float*)d_in[4];
    const float* rpd    = (const float*)d_in[5];
    const float* rph    = (const float*)d_in[6];
    const float* rpw    = (const float*)d_in[7];
    float* out = (float*)d_out;

    cudaFuncSetAttribute(flash_kernel,
                         cudaFuncAttributeMaxDynamicSharedMemorySize, FL_BYTES);

    prep_x<<<512, 256>>>(x);                               // launch 1
    prep_w<<<512, 256>>>(qkv_w, proj_w);                   // launch 2
    mm_fp16<0><<<dim3(32, 18), 256>>>(qkv_b, nullptr);     // launch 3
    flash_kernel<<<dim3(16, NHB), 256, FL_BYTES>>>(rpd, rph, rpw);  // launch 4 (ncu)
    mm_fp16<1><<<dim3(32, 6), 256>>>(proj_b, out);         // launch 5
}

// round 14
// speedup vs baseline: 1.2001x; 1.2001x over previous
#include <cuda_runtime.h>
#include <cuda_fp16.h>
#include <stdint.h>

// ---------------------------------------------------------------------------
// Attention3D on fp16 tensor cores (mma.sync m16n8k16, fp32 accumulate).
//   0) prep (2 kernels): x -> fp16; weights -> fp16 k-pair-interleaved
//   1) QKV GEMM -> Q/K/V fp16 natural [hb][n][c]
//   2) relpos: Q-row-resident, smem-table broadcast, coalesced j-major out
//   3) flash attention Br=128 Bc=64: tables from global; P in registers;
//      V natural via ldmatrix.trans
//   4) proj GEMM -> fp32 d_out
// ---------------------------------------------------------------------------

#define NHB  24
#define NSEQ 2048
#define HD   64
#define CDIM 768

__device__ __half  g_q[NHB * NSEQ * HD];
__device__ __half  g_k[NHB * NSEQ * HD];
__device__ __half  g_v[NHB * NSEQ * HD];        // natural [hb][n][c]
__device__ __half  g_attnout[4096 * CDIM];
__device__ __half  g_xr[4096 * CDIM];
__device__ __half2 g_qkvw[384 * 2304];          // [k/2][n] pairs
__device__ __half2 g_projw[384 * 768];
__device__ float   g_reld[NHB * 8 * NSEQ];      // [hb][kd][n]
__device__ float   g_relh[NHB * 16 * NSEQ];     // [hb][kh][n]
__device__ float   g_relw[NHB * 16 * NSEQ];     // [hb][kw][n]

// --- helpers ---------------------------------------------------------------
__device__ __forceinline__ void cpa16(void* dst, const void* src) {
    uint32_t d = (uint32_t)__cvta_generic_to_shared(dst);
    asm volatile("cp.async.cg.shared.global [%0], [%1], 16;" :: "r"(d), "l"(src));
}
__device__ __forceinline__ void cp_commit() {
    asm volatile("cp.async.commit_group;");
}
__device__ __forceinline__ void cp_wait0() {
    asm volatile("cp.async.wait_group 0;");
}
__device__ __forceinline__ void ldsm4(uint32_t r[4], const void* p) {
    uint32_t a = (uint32_t)__cvta_generic_to_shared(p);
    asm volatile("ldmatrix.sync.aligned.m8n8.x4.shared.b16 {%0,%1,%2,%3}, [%4];"
                 : "=r"(r[0]), "=r"(r[1]), "=r"(r[2]), "=r"(r[3]) : "r"(a));
}
__device__ __forceinline__ void ldsm4t(uint32_t r[4], const void* p) {
    uint32_t a = (uint32_t)__cvta_generic_to_shared(p);
    asm volatile("ldmatrix.sync.aligned.m8n8.x4.trans.shared.b16 {%0,%1,%2,%3}, [%4];"
                 : "=r"(r[0]), "=r"(r[1]), "=r"(r[2]), "=r"(r[3]) : "r"(a));
}
__device__ __forceinline__ void mma16(float d[4], const uint32_t a[4],
                                      uint32_t b0, uint32_t b1) {
    asm volatile(
        "mma.sync.aligned.m16n8k16.row.col.f32.f16.f16.f32 "
        "{%0,%1,%2,%3}, {%4,%5,%6,%7}, {%8,%9}, {%0,%1,%2,%3};"
        : "+f"(d[0]), "+f"(d[1]), "+f"(d[2]), "+f"(d[3])
        : "r"(a[0]), "r"(a[1]), "r"(a[2]), "r"(a[3]), "r"(b0), "r"(b1));
}
__device__ __forceinline__ uint32_t packh2(float lo, float hi) {
    __half2 h = __floats2half2_rn(lo, hi);
    return *(uint32_t*)&h;
}

// ---------------------------------------------------------------------------
// Prep kernels
// ---------------------------------------------------------------------------
__global__ void __launch_bounds__(256) prep_x(const float* __restrict__ x)
{
    const int stride = gridDim.x * 256;
    for (int f = blockIdx.x * 256 + threadIdx.x; f < (4096 * CDIM) / 4; f += stride) {
        float4 v = *(const float4*)&x[f * 4];
        *(uint2*)&g_xr[f * 4] = make_uint2(packh2(v.x, v.y), packh2(v.z, v.w));
    }
}
__global__ void __launch_bounds__(256) prep_w(const float* __restrict__ qw,
                                              const float* __restrict__ pw)
{
    const int stride = gridDim.x * 256;
    const int t = blockIdx.x * 256 + threadIdx.x;
    for (int i = t; i < 384 * 2304; i += stride) {
        const int k2 = i / 2304, n = i - k2 * 2304;
        g_qkvw[i] = __floats2half2_rn(qw[(2 * k2) * 2304 + n],
                                      qw[(2 * k2 + 1) * 2304 + n]);
    }
    for (int i = t; i < 384 * 768; i += stride) {
        const int k2 = i / 768, n = i - k2 * 768;
        g_projw[i] = __floats2half2_rn(pw[(2 * k2) * 768 + n],
                                       pw[(2 * k2 + 1) * 768 + n]);
    }
}

// ---------------------------------------------------------------------------
// fp16 GEMM: 128x128 tile, k-step 32 (24 iters), 2-stage cp.async.
// ---------------------------------------------------------------------------
template <int MODE>
__global__ void __launch_bounds__(256) mm_fp16(
    const float* __restrict__ bias, float* __restrict__ out)
{
    constexpr int N = (MODE == 0) ? 2304 : 768;
    __shared__ __half   As[2][128 * 40];
    __shared__ uint32_t Bs[2][16 * 136];
    const int tid = threadIdx.x, lane = tid & 31, w = tid >> 5;
    const int wm = w >> 1, wn = w & 1;
    const int bm = blockIdx.x * 128, bn = blockIdx.y * 128;
    const __half* Ap = (MODE == 0) ? g_xr : g_attnout;
    const uint32_t* Wp = (const uint32_t*)((MODE == 0) ? g_qkvw : g_projw);

    float c[2][8][4];
#pragma unroll
    for (int i = 0; i < 2; i++)
#pragma unroll
        for (int j = 0; j < 8; j++)
#pragma unroll
            for (int k = 0; k < 4; k++) c[i][j][k] = 0.f;

    auto stage = [&](int k0, int buf) {
        const int k20 = k0 >> 1;
#pragma unroll
        for (int it = 0; it < 2; it++) {
            const int i = tid + it * 256;
            const int r = i >> 2, c8 = (i & 3) << 3;
            cpa16(&As[buf][r * 40 + c8], &Ap[(bm + r) * 768 + k0 + c8]);
        }
#pragma unroll
        for (int it = 0; it < 2; it++) {
            const int i = tid + it * 256;
            const int kk = i >> 5, n4 = (i & 31) << 2;
            cpa16(&Bs[buf][kk * 136 + n4], &Wp[(k20 + kk) * N + bn + n4]);
        }
    };

    stage(0, 0); cp_commit();

    int buf = 0;
    for (int k0 = 0; k0 < 768; k0 += 32, buf ^= 1) {
        cp_wait0();
        __syncthreads();
        if (k0 + 32 < 768) { stage(k0 + 32, buf ^ 1); cp_commit(); }

        const uint32_t* bp = Bs[buf];
#pragma unroll
        for (int ks = 0; ks < 2; ks++) {
            uint32_t a0[4], a1[4];
            ldsm4(a0, &As[buf][(wm * 32 + ((lane >> 3) & 1) * 8 + (lane & 7)) * 40
                               + ks * 16 + (lane >> 4) * 8]);
            ldsm4(a1, &As[buf][(wm * 32 + 16 + ((lane >> 3) & 1) * 8 + (lane & 7)) * 40
                               + ks * 16 + (lane >> 4) * 8]);
#pragma unroll
            for (int nt = 0; nt < 8; nt++) {
                const int ncol = wn * 64 + nt * 8 + (lane >> 2);
                uint32_t b0 = bp[(ks * 8 + (lane & 3)) * 136 + ncol];
                uint32_t b1 = bp[(ks * 8 + 4 + (lane & 3)) * 136 + ncol];
                mma16(c[0][nt], a0, b0, b1);
                mma16(c[1][nt], a1, b0, b1);
            }
        }
        __syncthreads();
    }

    if (MODE == 0) {
        const int hc = bn + wn * 64;
        const int which = hc / 768;
        const int head = (hc % 768) >> 6;
        __half* dst = (which == 0) ? g_q : (which == 1) ? g_k : g_v;
#pragma unroll
        for (int mt = 0; mt < 2; mt++)
#pragma unroll
            for (int nt = 0; nt < 8; nt++) {
                const int ccol = nt * 8 + ((lane & 3) << 1);
                const float b0v = bias[hc + ccol];
                const float b1v = bias[hc + ccol + 1];
#pragma unroll
                for (int h = 0; h < 2; h++) {
                    const int row = bm + wm * 32 + mt * 16 + (lane >> 2) + 8 * h;
                    const int b_ = row >> 11, n = row & 2047;
                    const int hb = b_ * 12 + head;
                    *(__half2*)&dst[((size_t)(hb * NSEQ + n) << 6) + ccol] =
                        __floats2half2_rn(c[mt][nt][2 * h] + b0v,
                                          c[mt][nt][2 * h + 1] + b1v);
                }
            }
    } else {
#pragma unroll
        for (int mt = 0; mt < 2; mt++)
#pragma unroll
            for (int nt = 0; nt < 8; nt++) {
                const int col = bn + wn * 64 + nt * 8 + ((lane & 3) << 1);
                const float b0v = bias[col], b1v = bias[col + 1];
#pragma unroll
                for (int h = 0; h < 2; h++) {
                    const int row = bm + wm * 32 + mt * 16 + (lane >> 2) + 8 * h;
                    *(float2*)&out[row * 768 + col] =
                        make_float2(c[mt][nt][2 * h] + b0v, c[mt][nt][2 * h + 1] + b1v);
                }
            }
    }
}

// ---------------------------------------------------------------------------
// Rel-pos tables: one thread per (hb, n).  Q row resident in registers;
// all 77 table rows in smem (broadcast LDS); coalesced j-major writes.
// ---------------------------------------------------------------------------
__global__ void __launch_bounds__(256) relpos_kernel(
    const float* __restrict__ rpd, const float* __restrict__ rph,
    const float* __restrict__ rpw)
{
    __shared__ float T[77 * 64];     // rows 0-14 rpd | 15-45 rph | 46-76 rpw
    const int tid = threadIdx.x;
    for (int i = tid; i < 77 * 16; i += 256) {
        const int r = i >> 4, c4 = (i & 15) << 2;
        const float* src = (r < 15) ? &rpd[r * 64]
                         : (r < 46) ? &rph[(r - 15) * 64]
                                    : &rpw[(r - 46) * 64];
        *(float4*)&T[r * 64 + c4] = *(const float4*)&src[c4];
    }
    __syncthreads();

    const int idx = blockIdx.x * 256 + tid;      // 24*2048 threads
    const int n = idx & 2047, hb = idx >> 11;

    // Q row -> 64 fp32 registers
    float q[64];
    const __half2* q2 = (const __half2*)&g_q[(size_t)(hb * NSEQ + n) * HD];
#pragma unroll
    for (int i = 0; i < 32; i++) {
        float2 f = __half22float2(q2[i]);
        q[2 * i] = f.x; q[2 * i + 1] = f.y;
    }

    const int d = n >> 8, h = (n >> 4) & 15, wq = n & 15;
    auto dot = [&](const float* t) {
        float s = 0.f;
#pragma unroll
        for (int c4 = 0; c4 < 16; c4++) {
            float4 t4 = *(const float4*)&t[c4 * 4];
            s += q[4 * c4] * t4.x + q[4 * c4 + 1] * t4.y
               + q[4 * c4 + 2] * t4.z + q[4 * c4 + 3] * t4.w;
        }
        return s;
    };

#pragma unroll
    for (int kd = 0; kd < 8; kd++)
        g_reld[(hb * 8 + kd) * NSEQ + n] = dot(&T[(d - kd + 7) * 64]);
#pragma unroll
    for (int kh = 0; kh < 16; kh++)
        g_relh[(hb * 16 + kh) * NSEQ + n] = dot(&T[(15 + h - kh + 15) * 64]);
#pragma unroll
    for (int kw = 0; kw < 16; kw++)
        g_relw[(hb * 16 + kw) * NSEQ + n] = dot(&T[(46 + wq - kw + 15) * 64]);
}

// ---------------------------------------------------------------------------
// Flash attention fp16: Br=128, Bc=64, 8 warps, 32 iters.
// Tables from global (coalesced); P in registers; V via ldmatrix.trans.
// smem: Qh 128x72h=18432 | K 2x64x72h=18432 | V 2x64x72h=18432 |
//       rDt 4096 | rHt 8192 | rWt 8192  = 75776 B   (2 CTAs/SM)
// ---------------------------------------------------------------------------
#define FL_BYTES 75776

__global__ void __launch_bounds__(256, 2) flash_kernel()
{
    extern __shared__ char smc[];
    __half* Qh = (__half*)smc;                    // pitch 72
    __half* Kh = (__half*)(smc + 18432);
    __half* Vh = (__half*)(smc + 36864);
    float* rDt = (float*)(smc + 55296);
    float* rHt = (float*)(smc + 59392);
    float* rWt = (float*)(smc + 67584);

    const int tid = threadIdx.x, lane = tid & 31, w = tid >> 5;
    const int hb = blockIdx.y;
    const int qbase = blockIdx.x * 128;
    const float scale = 0.125f;

    auto stageKV = [&](int kt, int buf) {
        const __half* Kg = &g_k[(size_t)(hb * NSEQ + kt * 64) * HD];
        const __half* Vg = &g_v[(size_t)(hb * NSEQ + kt * 64) * HD];
        __half* Kb = Kh + buf * 4608;
        __half* Vb = Vh + buf * 4608;
#pragma unroll
        for (int it = 0; it < 2; it++) {
            const int i = tid + it * 256;
            const int r = i >> 3, c8 = (i & 7) << 3;
            cpa16(&Kb[r * 72 + c8], &Kg[r * 64 + c8]);
            cpa16(&Vb[r * 72 + c8], &Vg[r * 64 + c8]);
        }
    };

    stageKV(0, 0); cp_commit();

    // --- stage Q ---
    const __half* Qg = &g_q[(size_t)(hb * NSEQ + qbase) * HD];
#pragma unroll
    for (int it = 0; it < 4; it++) {
        const int i = tid + it * 256;
        const int r = i >> 3, c8 = (i & 7) << 3;
        *(uint4*)&Qh[r * 72 + c8] = *(const uint4*)&Qg[r * 64 + c8];
    }

    // --- load precomputed bias tables (coalesced float4) ---
    {
        const float* srcD = &g_reld[(size_t)hb * 8 * NSEQ + qbase];
        for (int i = tid; i < 256; i += 256) {
            const int j = i >> 5, r4 = (i & 31) << 2;
            *(float4*)&rDt[j * 128 + r4] = *(const float4*)&srcD[j * NSEQ + r4];
        }
        const float* srcH = &g_relh[(size_t)hb * 16 * NSEQ + qbase];
        const float* srcW = &g_relw[(size_t)hb * 16 * NSEQ + qbase];
        for (int i = tid; i < 512; i += 256) {
            const int j = i >> 5, r4 = (i & 31) << 2;
            *(float4*)&rHt[j * 128 + r4] = *(const float4*)&srcH[j * NSEQ + r4];
            *(float4*)&rWt[j * 128 + r4] = *(const float4*)&srcW[j * NSEQ + r4];
        }
    }
    __syncthreads();

    // --- hoist Q A-fragments + per-thread rW values ---
    uint32_t aq[4][4];
#pragma unroll
    for (int ksp = 0; ksp < 4; ksp++)
        ldsm4(aq[ksp], &Qh[(w * 16 + ((lane >> 3) & 1) * 8 + (lane & 7)) * 72
                           + ksp * 16 + (lane >> 4) * 8]);
    int rq[2];
    rq[0] = w * 16 + (lane >> 2);
    rq[1] = rq[0] + 8;
    float rw[2][2][2];
#pragma unroll
    for (int p = 0; p < 2; p++)
#pragma unroll
        for (int j2 = 0; j2 < 2; j2++)
#pragma unroll
            for (int h = 0; h < 2; h++)
                rw[p][j2][h] = rWt[(8 * p + 2 * (lane & 3) + j2) * 128 + rq[h]];

    float m[2] = {-1e30f, -1e30f}, l[2] = {0.f, 0.f};
    float o[8][4];
#pragma unroll
    for (int i = 0; i < 8; i++)
#pragma unroll
        for (int j = 0; j < 4; j++) o[i][j] = 0.f;

    int buf = 0;
    for (int kt = 0; kt < 32; kt++, buf ^= 1) {
        cp_wait0();
        __syncthreads();
        if (kt + 1 < 32) { stageKV(kt + 1, buf ^ 1); cp_commit(); }
        const __half* Kb = Kh + buf * 4608;
        const __half* Vb = Vh + buf * 4608;

        // --- S = Q K^T ---
        float s[8][4];
#pragma unroll
        for (int i = 0; i < 8; i++)
#pragma unroll
            for (int j = 0; j < 4; j++) s[i][j] = 0.f;
#pragma unroll
        for (int kp = 0; kp < 2; kp++) {
#pragma unroll
            for (int nt = 0; nt < 8; nt++) {
                uint32_t k4[4];
                ldsm4(k4, &Kb[(nt * 8 + (lane & 7)) * 72 + kp * 32 + (lane >> 3) * 8]);
                mma16(s[nt], aq[2 * kp], k4[0], k4[1]);
                mma16(s[nt], aq[2 * kp + 1], k4[2], k4[3]);
            }
        }

        // --- scale + bias ---
        const int kd = kt >> 2;
        float bh[4][2];
#pragma unroll
        for (int g = 0; g < 4; g++)
#pragma unroll
            for (int h = 0; h < 2; h++)
                bh[g][h] = rDt[kd * 128 + rq[h]]
                         + rHt[((kt & 3) * 4 + g) * 128 + rq[h]];
#pragma unroll
        for (int nt = 0; nt < 8; nt++)
#pragma unroll
            for (int h = 0; h < 2; h++)
#pragma unroll
                for (int j2 = 0; j2 < 2; j2++)
                    s[nt][2 * h + j2] = fmaf(s[nt][2 * h + j2], scale,
                                             bh[nt >> 1][h] + rw[nt & 1][j2][h]);

        // --- online softmax ---
#pragma unroll
        for (int h = 0; h < 2; h++) {
            float rmax = s[0][2 * h];
#pragma unroll
            for (int nt = 0; nt < 8; nt++) {
                rmax = fmaxf(rmax, s[nt][2 * h]);
                rmax = fmaxf(rmax, s[nt][2 * h + 1]);
            }
            rmax = fmaxf(rmax, __shfl_xor_sync(0xffffffffu, rmax, 1));
            rmax = fmaxf(rmax, __shfl_xor_sync(0xffffffffu, rmax, 2));
            const float mn = fmaxf(m[h], rmax);
            const float corr = __expf(m[h] - mn);
            m[h] = mn;
            float rs = 0.f;
#pragma unroll
            for (int nt = 0; nt < 8; nt++) {
                s[nt][2 * h]     = __expf(s[nt][2 * h] - mn);
                s[nt][2 * h + 1] = __expf(s[nt][2 * h + 1] - mn);
                rs += s[nt][2 * h] + s[nt][2 * h + 1];
            }
            rs += __shfl_xor_sync(0xffffffffu, rs, 1);
            rs += __shfl_xor_sync(0xffffffffu, rs, 2);
            l[h] = l[h] * corr + rs;
#pragma unroll
            for (int nt = 0; nt < 8; nt++) {
                o[nt][2 * h] *= corr;
                o[nt][2 * h + 1] *= corr;
            }
        }

        // --- pack P as A-fragments (C-frag layout == A-frag layout) ---
        uint32_t pa[4][4];
#pragma unroll
        for (int kc = 0; kc < 4; kc++) {
            pa[kc][0] = packh2(s[2 * kc][0],     s[2 * kc][1]);
            pa[kc][1] = packh2(s[2 * kc][2],     s[2 * kc][3]);
            pa[kc][2] = packh2(s[2 * kc + 1][0], s[2 * kc + 1][1]);
            pa[kc][3] = packh2(s[2 * kc + 1][2], s[2 * kc + 1][3]);
        }

        // --- O += P V : V natural [key][c], B-frags via ldmatrix.trans ---
#pragma unroll
        for (int kp = 0; kp < 4; kp++) {
#pragma unroll
            for (int cb = 0; cb < 4; cb++) {
                uint32_t v4[4];
                ldsm4t(v4, &Vb[(kp * 16 + ((lane >> 3) & 1) * 8 + (lane & 7)) * 72
                               + cb * 16 + (lane >> 4) * 8]);
                mma16(o[2 * cb],     pa[kp], v4[0], v4[1]);
                mma16(o[2 * cb + 1], pa[kp], v4[2], v4[3]);
            }
        }
    }

    // --- finalize: fp16 attnout (proj A operand) ---
    const int b = hb / 12, head = hb % 12;
#pragma unroll
    for (int h = 0; h < 2; h++) {
        const float inv = 1.0f / l[h];
        const int qg = qbase + rq[h];
        __half* orow = &g_attnout[(size_t)(b * NSEQ + qg) * CDIM + head * 64];
#pragma unroll
        for (int nt = 0; nt < 8; nt++)
            *(__half2*)&orow[nt * 8 + 2 * (lane & 3)] =
                __floats2half2_rn(o[nt][2 * h] * inv, o[nt][2 * h + 1] * inv);
    }
}

// ---------------------------------------------------------------------------
extern "C" void kernel_launch(void* const* d_in, const int* in_sizes, int n_in,
                              void* d_out, int out_size)
{
    const float* x      = (const float*)d_in[0];
    const float* qkv_w  = (const float*)d_in[1];
    const float* qkv_b  = (const float*)d_in[2];
    const float* proj_w = (const float*)d_in[3];
    const float* proj_b = (const float*)d_in[4];
    const float* rpd    = (const float*)d_in[5];
    const float* rph    = (const float*)d_in[6];
    const float* rpw    = (const float*)d_in[7];
    float* out = (float*)d_out;

    cudaFuncSetAttribute(flash_kernel,
                         cudaFuncAttributeMaxDynamicSharedMemorySize, FL_BYTES);

    prep_x<<<512, 256>>>(x);                               // launch 1
    prep_w<<<512, 256>>>(qkv_w, proj_w);                   // launch 2
    mm_fp16<0><<<dim3(32, 18), 256>>>(qkv_b, nullptr);     // launch 3
    relpos_kernel<<<192, 256>>>(rpd, rph, rpw);            // launch 4 (ncu)
    flash_kernel<<<dim3(16, NHB), 256, FL_BYTES>>>();      // launch 5
    mm_fp16<1><<<dim3(32, 6), 256>>>(proj_b, out);         // launch 6
}

// round 15
// speedup vs baseline: 1.4835x; 1.2361x over previous
#include <cuda_runtime.h>
#include <cuda_fp16.h>
#include <stdint.h>

// ---------------------------------------------------------------------------
// Attention3D on fp16 tensor cores (mma.sync m16n8k16, fp32 accumulate).
//   0) prep (2 kernels): x -> fp16; weights -> fp16 k-pair-interleaved
//   1) QKV GEMM -> Q/K/V fp16 natural [hb][n][c]
//   2) relpos: contiguous-row register-tiled matvecs (ILP 8/16 per step)
//   3) flash attention Br=128 Bc=64: tables from global; P in registers;
//      V natural via ldmatrix.trans
//   4) proj GEMM -> fp32 d_out
// ---------------------------------------------------------------------------

#define NHB  24
#define NSEQ 2048
#define HD   64
#define CDIM 768

__device__ __half  g_q[NHB * NSEQ * HD];
__device__ __half  g_k[NHB * NSEQ * HD];
__device__ __half  g_v[NHB * NSEQ * HD];        // natural [hb][n][c]
__device__ __half  g_attnout[4096 * CDIM];
__device__ __half  g_xr[4096 * CDIM];
__device__ __half2 g_qkvw[384 * 2304];          // [k/2][n] pairs
__device__ __half2 g_projw[384 * 768];
__device__ float   g_reld[NHB * 8 * NSEQ];      // [hb][kd][n]
__device__ float   g_relh[NHB * 16 * NSEQ];     // [hb][kh][n]
__device__ float   g_relw[NHB * 16 * NSEQ];     // [hb][kw][n]

// --- helpers ---------------------------------------------------------------
__device__ __forceinline__ void cpa16(void* dst, const void* src) {
    uint32_t d = (uint32_t)__cvta_generic_to_shared(dst);
    asm volatile("cp.async.cg.shared.global [%0], [%1], 16;" :: "r"(d), "l"(src));
}
__device__ __forceinline__ void cp_commit() {
    asm volatile("cp.async.commit_group;");
}
__device__ __forceinline__ void cp_wait0() {
    asm volatile("cp.async.wait_group 0;");
}
__device__ __forceinline__ void ldsm4(uint32_t r[4], const void* p) {
    uint32_t a = (uint32_t)__cvta_generic_to_shared(p);
    asm volatile("ldmatrix.sync.aligned.m8n8.x4.shared.b16 {%0,%1,%2,%3}, [%4];"
                 : "=r"(r[0]), "=r"(r[1]), "=r"(r[2]), "=r"(r[3]) : "r"(a));
}
__device__ __forceinline__ void ldsm4t(uint32_t r[4], const void* p) {
    uint32_t a = (uint32_t)__cvta_generic_to_shared(p);
    asm volatile("ldmatrix.sync.aligned.m8n8.x4.trans.shared.b16 {%0,%1,%2,%3}, [%4];"
                 : "=r"(r[0]), "=r"(r[1]), "=r"(r[2]), "=r"(r[3]) : "r"(a));
}
__device__ __forceinline__ void mma16(float d[4], const uint32_t a[4],
                                      uint32_t b0, uint32_t b1) {
    asm volatile(
        "mma.sync.aligned.m16n8k16.row.col.f32.f16.f16.f32 "
        "{%0,%1,%2,%3}, {%4,%5,%6,%7}, {%8,%9}, {%0,%1,%2,%3};"
        : "+f"(d[0]), "+f"(d[1]), "+f"(d[2]), "+f"(d[3])
        : "r"(a[0]), "r"(a[1]), "r"(a[2]), "r"(a[3]), "r"(b0), "r"(b1));
}
__device__ __forceinline__ uint32_t packh2(float lo, float hi) {
    __half2 h = __floats2half2_rn(lo, hi);
    return *(uint32_t*)&h;
}

// ---------------------------------------------------------------------------
// Prep kernels
// ---------------------------------------------------------------------------
__global__ void __launch_bounds__(256) prep_x(const float* __restrict__ x)
{
    const int stride = gridDim.x * 256;
    for (int f = blockIdx.x * 256 + threadIdx.x; f < (4096 * CDIM) / 4; f += stride) {
        float4 v = *(const float4*)&x[f * 4];
        *(uint2*)&g_xr[f * 4] = make_uint2(packh2(v.x, v.y), packh2(v.z, v.w));
    }
}
__global__ void __launch_bounds__(256) prep_w(const float* __restrict__ qw,
                                              const float* __restrict__ pw)
{
    const int stride = gridDim.x * 256;
    const int t = blockIdx.x * 256 + threadIdx.x;
    for (int i = t; i < 384 * 2304; i += stride) {
        const int k2 = i / 2304, n = i - k2 * 2304;
        g_qkvw[i] = __floats2half2_rn(qw[(2 * k2) * 2304 + n],
                                      qw[(2 * k2 + 1) * 2304 + n]);
    }
    for (int i = t; i < 384 * 768; i += stride) {
        const int k2 = i / 768, n = i - k2 * 768;
        g_projw[i] = __floats2half2_rn(pw[(2 * k2) * 768 + n],
                                       pw[(2 * k2 + 1) * 768 + n]);
    }
}

// ---------------------------------------------------------------------------
// fp16 GEMM: 128x128 tile, k-step 32 (24 iters), 2-stage cp.async.
// ---------------------------------------------------------------------------
template <int MODE>
__global__ void __launch_bounds__(256) mm_fp16(
    const float* __restrict__ bias, float* __restrict__ out)
{
    constexpr int N = (MODE == 0) ? 2304 : 768;
    __shared__ __half   As[2][128 * 40];
    __shared__ uint32_t Bs[2][16 * 136];
    const int tid = threadIdx.x, lane = tid & 31, w = tid >> 5;
    const int wm = w >> 1, wn = w & 1;
    const int bm = blockIdx.x * 128, bn = blockIdx.y * 128;
    const __half* Ap = (MODE == 0) ? g_xr : g_attnout;
    const uint32_t* Wp = (const uint32_t*)((MODE == 0) ? g_qkvw : g_projw);

    float c[2][8][4];
#pragma unroll
    for (int i = 0; i < 2; i++)
#pragma unroll
        for (int j = 0; j < 8; j++)
#pragma unroll
            for (int k = 0; k < 4; k++) c[i][j][k] = 0.f;

    auto stage = [&](int k0, int buf) {
        const int k20 = k0 >> 1;
#pragma unroll
        for (int it = 0; it < 2; it++) {
            const int i = tid + it * 256;
            const int r = i >> 2, c8 = (i & 3) << 3;
            cpa16(&As[buf][r * 40 + c8], &Ap[(bm + r) * 768 + k0 + c8]);
        }
#pragma unroll
        for (int it = 0; it < 2; it++) {
            const int i = tid + it * 256;
            const int kk = i >> 5, n4 = (i & 31) << 2;
            cpa16(&Bs[buf][kk * 136 + n4], &Wp[(k20 + kk) * N + bn + n4]);
        }
    };

    stage(0, 0); cp_commit();

    int buf = 0;
    for (int k0 = 0; k0 < 768; k0 += 32, buf ^= 1) {
        cp_wait0();
        __syncthreads();
        if (k0 + 32 < 768) { stage(k0 + 32, buf ^ 1); cp_commit(); }

        const uint32_t* bp = Bs[buf];
#pragma unroll
        for (int ks = 0; ks < 2; ks++) {
            uint32_t a0[4], a1[4];
            ldsm4(a0, &As[buf][(wm * 32 + ((lane >> 3) & 1) * 8 + (lane & 7)) * 40
                               + ks * 16 + (lane >> 4) * 8]);
            ldsm4(a1, &As[buf][(wm * 32 + 16 + ((lane >> 3) & 1) * 8 + (lane & 7)) * 40
                               + ks * 16 + (lane >> 4) * 8]);
#pragma unroll
            for (int nt = 0; nt < 8; nt++) {
                const int ncol = wn * 64 + nt * 8 + (lane >> 2);
                uint32_t b0 = bp[(ks * 8 + (lane & 3)) * 136 + ncol];
                uint32_t b1 = bp[(ks * 8 + 4 + (lane & 3)) * 136 + ncol];
                mma16(c[0][nt], a0, b0, b1);
                mma16(c[1][nt], a1, b0, b1);
            }
        }
        __syncthreads();
    }

    if (MODE == 0) {
        const int hc = bn + wn * 64;
        const int which = hc / 768;
        const int head = (hc % 768) >> 6;
        __half* dst = (which == 0) ? g_q : (which == 1) ? g_k : g_v;
#pragma unroll
        for (int mt = 0; mt < 2; mt++)
#pragma unroll
            for (int nt = 0; nt < 8; nt++) {
                const int ccol = nt * 8 + ((lane & 3) << 1);
                const float b0v = bias[hc + ccol];
                const float b1v = bias[hc + ccol + 1];
#pragma unroll
                for (int h = 0; h < 2; h++) {
                    const int row = bm + wm * 32 + mt * 16 + (lane >> 2) + 8 * h;
                    const int b_ = row >> 11, n = row & 2047;
                    const int hb = b_ * 12 + head;
                    *(__half2*)&dst[((size_t)(hb * NSEQ + n) << 6) + ccol] =
                        __floats2half2_rn(c[mt][nt][2 * h] + b0v,
                                          c[mt][nt][2 * h + 1] + b1v);
                }
            }
    } else {
#pragma unroll
        for (int mt = 0; mt < 2; mt++)
#pragma unroll
            for (int nt = 0; nt < 8; nt++) {
                const int col = bn + wn * 64 + nt * 8 + ((lane & 3) << 1);
                const float b0v = bias[col], b1v = bias[col + 1];
#pragma unroll
                for (int h = 0; h < 2; h++) {
                    const int row = bm + wm * 32 + mt * 16 + (lane >> 2) + 8 * h;
                    *(float2*)&out[row * 768 + col] =
                        make_float2(c[mt][nt][2 * h] + b0v, c[mt][nt][2 * h + 1] + b1v);
                }
            }
    }
}

// ---------------------------------------------------------------------------
// Rel-pos tables.  One thread per (hb, n); Q row in registers; tables in
// smem (pitch 68).  Needed rows are CONTIGUOUS ranges per group, so each
// group is a register-tiled matvec: per c4 step one q float4 feeds 8/16
// INDEPENDENT accumulators (ILP hides LDS/FMA latency).
//   kd: rows [d, d+7]       (row d+i -> kd = 7-i)
//   kh: rows [15+h, 30+h]   (row 15+h+i -> kh = 15-i)
//   kw: rows [46+wq, 61+wq] (row 46+wq+i -> kw = 15-i)
// ---------------------------------------------------------------------------
#define TP 68
__global__ void __launch_bounds__(256) relpos_kernel(
    const float* __restrict__ rpd, const float* __restrict__ rph,
    const float* __restrict__ rpw)
{
    __shared__ float T[77 * TP];     // rows 0-14 rpd | 15-45 rph | 46-76 rpw
    const int tid = threadIdx.x;
    for (int i = tid; i < 77 * 16; i += 256) {
        const int r = i >> 4, c4 = (i & 15) << 2;
        const float* src = (r < 15) ? &rpd[r * 64]
                         : (r < 46) ? &rph[(r - 15) * 64]
                                    : &rpw[(r - 46) * 64];
        *(float4*)&T[r * TP + c4] = *(const float4*)&src[c4];
    }
    __syncthreads();

    const int idx = blockIdx.x * 256 + tid;      // 24*2048 threads
    const int n = idx & 2047, hb = idx >> 11;

    float q[64];
    const __half2* q2 = (const __half2*)&g_q[(size_t)(hb * NSEQ + n) * HD];
#pragma unroll
    for (int i = 0; i < 32; i++) {
        float2 f = __half22float2(q2[i]);
        q[2 * i] = f.x; q[2 * i + 1] = f.y;
    }

    const int d = n >> 8, h = (n >> 4) & 15, wq = n & 15;

    // --- kd group: 8 independent accumulators ---
    {
        float acc[8] = {};
        const float* Tb = &T[d * TP];
#pragma unroll
        for (int c4 = 0; c4 < 16; c4++) {
            const float q0 = q[4 * c4], q1 = q[4 * c4 + 1];
            const float q2v = q[4 * c4 + 2], q3 = q[4 * c4 + 3];
#pragma unroll
            for (int i = 0; i < 8; i++) {
                float4 t = *(const float4*)&Tb[i * TP + c4 * 4];
                acc[i] += q0 * t.x + q1 * t.y + q2v * t.z + q3 * t.w;
            }
        }
#pragma unroll
        for (int i = 0; i < 8; i++)
            g_reld[(hb * 8 + (7 - i)) * NSEQ + n] = acc[i];
    }
    // --- kh group: 16 accumulators ---
    {
        float acc[16] = {};
        const float* Tb = &T[(15 + h) * TP];
#pragma unroll
        for (int c4 = 0; c4 < 16; c4++) {
            const float q0 = q[4 * c4], q1 = q[4 * c4 + 1];
            const float q2v = q[4 * c4 + 2], q3 = q[4 * c4 + 3];
#pragma unroll
            for (int i = 0; i < 16; i++) {
                float4 t = *(const float4*)&Tb[i * TP + c4 * 4];
                acc[i] += q0 * t.x + q1 * t.y + q2v * t.z + q3 * t.w;
            }
        }
#pragma unroll
        for (int i = 0; i < 16; i++)
            g_relh[(hb * 16 + (15 - i)) * NSEQ + n] = acc[i];
    }
    // --- kw group: 16 accumulators ---
    {
        float acc[16] = {};
        const float* Tb = &T[(46 + wq) * TP];
#pragma unroll
        for (int c4 = 0; c4 < 16; c4++) {
            const float q0 = q[4 * c4], q1 = q[4 * c4 + 1];
            const float q2v = q[4 * c4 + 2], q3 = q[4 * c4 + 3];
#pragma unroll
            for (int i = 0; i < 16; i++) {
                float4 t = *(const float4*)&Tb[i * TP + c4 * 4];
                acc[i] += q0 * t.x + q1 * t.y + q2v * t.z + q3 * t.w;
            }
        }
#pragma unroll
        for (int i = 0; i < 16; i++)
            g_relw[(hb * 16 + (15 - i)) * NSEQ + n] = acc[i];
    }
}

// ---------------------------------------------------------------------------
// Flash attention fp16: Br=128, Bc=64, 8 warps, 32 iters.
// Tables from global (coalesced); P in registers; V via ldmatrix.trans.
// smem: Qh 128x72h=18432 | K 2x64x72h=18432 | V 2x64x72h=18432 |
//       rDt 4096 | rHt 8192 | rWt 8192  = 75776 B   (2 CTAs/SM)
// ---------------------------------------------------------------------------
#define FL_BYTES 75776

__global__ void __launch_bounds__(256, 2) flash_kernel()
{
    extern __shared__ char smc[];
    __half* Qh = (__half*)smc;                    // pitch 72
    __half* Kh = (__half*)(smc + 18432);
    __half* Vh = (__half*)(smc + 36864);
    float* rDt = (float*)(smc + 55296);
    float* rHt = (float*)(smc + 59392);
    float* rWt = (float*)(smc + 67584);

    const int tid = threadIdx.x, lane = tid & 31, w = tid >> 5;
    const int hb = blockIdx.y;
    const int qbase = blockIdx.x * 128;
    const float scale = 0.125f;

    auto stageKV = [&](int kt, int buf) {
        const __half* Kg = &g_k[(size_t)(hb * NSEQ + kt * 64) * HD];
        const __half* Vg = &g_v[(size_t)(hb * NSEQ + kt * 64) * HD];
        __half* Kb = Kh + buf * 4608;
        __half* Vb = Vh + buf * 4608;
#pragma unroll
        for (int it = 0; it < 2; it++) {
            const int i = tid + it * 256;
            const int r = i >> 3, c8 = (i & 7) << 3;
            cpa16(&Kb[r * 72 + c8], &Kg[r * 64 + c8]);
            cpa16(&Vb[r * 72 + c8], &Vg[r * 64 + c8]);
        }
    };

    stageKV(0, 0); cp_commit();

    // --- stage Q ---
    const __half* Qg = &g_q[(size_t)(hb * NSEQ + qbase) * HD];
#pragma unroll
    for (int it = 0; it < 4; it++) {
        const int i = tid + it * 256;
        const int r = i >> 3, c8 = (i & 7) << 3;
        *(uint4*)&Qh[r * 72 + c8] = *(const uint4*)&Qg[r * 64 + c8];
    }

    // --- load precomputed bias tables (coalesced float4) ---
    {
        const float* srcD = &g_reld[(size_t)hb * 8 * NSEQ + qbase];
        for (int i = tid; i < 256; i += 256) {
            const int j = i >> 5, r4 = (i & 31) << 2;
            *(float4*)&rDt[j * 128 + r4] = *(const float4*)&srcD[j * NSEQ + r4];
        }
        const float* srcH = &g_relh[(size_t)hb * 16 * NSEQ + qbase];
        const float* srcW = &g_relw[(size_t)hb * 16 * NSEQ + qbase];
        for (int i = tid; i < 512; i += 256) {
            const int j = i >> 5, r4 = (i & 31) << 2;
            *(float4*)&rHt[j * 128 + r4] = *(const float4*)&srcH[j * NSEQ + r4];
            *(float4*)&rWt[j * 128 + r4] = *(const float4*)&srcW[j * NSEQ + r4];
        }
    }
    __syncthreads();

    // --- hoist Q A-fragments + per-thread rW values ---
    uint32_t aq[4][4];
#pragma unroll
    for (int ksp = 0; ksp < 4; ksp++)
        ldsm4(aq[ksp], &Qh[(w * 16 + ((lane >> 3) & 1) * 8 + (lane & 7)) * 72
                           + ksp * 16 + (lane >> 4) * 8]);
    int rq[2];
    rq[0] = w * 16 + (lane >> 2);
    rq[1] = rq[0] + 8;
    float rw[2][2][2];
#pragma unroll
    for (int p = 0; p < 2; p++)
#pragma unroll
        for (int j2 = 0; j2 < 2; j2++)
#pragma unroll
            for (int h = 0; h < 2; h++)
                rw[p][j2][h] = rWt[(8 * p + 2 * (lane & 3) + j2) * 128 + rq[h]];

    float m[2] = {-1e30f, -1e30f}, l[2] = {0.f, 0.f};
    float o[8][4];
#pragma unroll
    for (int i = 0; i < 8; i++)
#pragma unroll
        for (int j = 0; j < 4; j++) o[i][j] = 0.f;

    int buf = 0;
    for (int kt = 0; kt < 32; kt++, buf ^= 1) {
        cp_wait0();
        __syncthreads();
        if (kt + 1 < 32) { stageKV(kt + 1, buf ^ 1); cp_commit(); }
        const __half* Kb = Kh + buf * 4608;
        const __half* Vb = Vh + buf * 4608;

        // --- S = Q K^T ---
        float s[8][4];
#pragma unroll
        for (int i = 0; i < 8; i++)
#pragma unroll
            for (int j = 0; j < 4; j++) s[i][j] = 0.f;
#pragma unroll
        for (int kp = 0; kp < 2; kp++) {
#pragma unroll
            for (int nt = 0; nt < 8; nt++) {
                uint32_t k4[4];
                ldsm4(k4, &Kb[(nt * 8 + (lane & 7)) * 72 + kp * 32 + (lane >> 3) * 8]);
                mma16(s[nt], aq[2 * kp], k4[0], k4[1]);
                mma16(s[nt], aq[2 * kp + 1], k4[2], k4[3]);
            }
        }

        // --- scale + bias ---
        const int kd = kt >> 2;
        float bh[4][2];
#pragma unroll
        for (int g = 0; g < 4; g++)
#pragma unroll
            for (int h = 0; h < 2; h++)
                bh[g][h] = rDt[kd * 128 + rq[h]]
                         + rHt[((kt & 3) * 4 + g) * 128 + rq[h]];
#pragma unroll
        for (int nt = 0; nt < 8; nt++)
#pragma unroll
            for (int h = 0; h < 2; h++)
#pragma unroll
                for (int j2 = 0; j2 < 2; j2++)
                    s[nt][2 * h + j2] = fmaf(s[nt][2 * h + j2], scale,
                                             bh[nt >> 1][h] + rw[nt & 1][j2][h]);

        // --- online softmax ---
#pragma unroll
        for (int h = 0; h < 2; h++) {
            float rmax = s[0][2 * h];
#pragma unroll
            for (int nt = 0; nt < 8; nt++) {
                rmax = fmaxf(rmax, s[nt][2 * h]);
                rmax = fmaxf(rmax, s[nt][2 * h + 1]);
            }
            rmax = fmaxf(rmax, __shfl_xor_sync(0xffffffffu, rmax, 1));
            rmax = fmaxf(rmax, __shfl_xor_sync(0xffffffffu, rmax, 2));
            const float mn = fmaxf(m[h], rmax);
            const float corr = __expf(m[h] - mn);
            m[h] = mn;
            float rs = 0.f;
#pragma unroll
            for (int nt = 0; nt < 8; nt++) {
                s[nt][2 * h]     = __expf(s[nt][2 * h] - mn);
                s[nt][2 * h + 1] = __expf(s[nt][2 * h + 1] - mn);
                rs += s[nt][2 * h] + s[nt][2 * h + 1];
            }
            rs += __shfl_xor_sync(0xffffffffu, rs, 1);
            rs += __shfl_xor_sync(0xffffffffu, rs, 2);
            l[h] = l[h] * corr + rs;
#pragma unroll
            for (int nt = 0; nt < 8; nt++) {
                o[nt][2 * h] *= corr;
                o[nt][2 * h + 1] *= corr;
            }
        }

        // --- pack P as A-fragments (C-frag layout == A-frag layout) ---
        uint32_t pa[4][4];
#pragma unroll
        for (int kc = 0; kc < 4; kc++) {
            pa[kc][0] = packh2(s[2 * kc][0],     s[2 * kc][1]);
            pa[kc][1] = packh2(s[2 * kc][2],     s[2 * kc][3]);
            pa[kc][2] = packh2(s[2 * kc + 1][0], s[2 * kc + 1][1]);
            pa[kc][3] = packh2(s[2 * kc + 1][2], s[2 * kc + 1][3]);
        }

        // --- O += P V : V natural [key][c], B-frags via ldmatrix.trans ---
#pragma unroll
        for (int kp = 0; kp < 4; kp++) {
#pragma unroll
            for (int cb = 0; cb < 4; cb++) {
                uint32_t v4[4];
                ldsm4t(v4, &Vb[(kp * 16 + ((lane >> 3) & 1) * 8 + (lane & 7)) * 72
                               + cb * 16 + (lane >> 4) * 8]);
                mma16(o[2 * cb],     pa[kp], v4[0], v4[1]);
                mma16(o[2 * cb + 1], pa[kp], v4[2], v4[3]);
            }
        }
    }

    // --- finalize: fp16 attnout (proj A operand) ---
    const int b = hb / 12, head = hb % 12;
#pragma unroll
    for (int h = 0; h < 2; h++) {
        const float inv = 1.0f / l[h];
        const int qg = qbase + rq[h];
        __half* orow = &g_attnout[(size_t)(b * NSEQ + qg) * CDIM + head * 64];
#pragma unroll
        for (int nt = 0; nt < 8; nt++)
            *(__half2*)&orow[nt * 8 + 2 * (lane & 3)] =
                __floats2half2_rn(o[nt][2 * h] * inv, o[nt][2 * h + 1] * inv);
    }
}

// ---------------------------------------------------------------------------
extern "C" void kernel_launch(void* const* d_in, const int* in_sizes, int n_in,
                              void* d_out, int out_size)
{
    const float* x      = (const float*)d_in[0];
    const float* qkv_w  = (const float*)d_in[1];
    const float* qkv_b  = (const float*)d_in[2];
    const float* proj_w = (const float*)d_in[3];
    const float* proj_b = (const float*)d_in[4];
    const float* rpd    = (const float*)d_in[5];
    const float* rph    = (const float*)d_in[6];
    const float* rpw    = (const float*)d_in[7];
    float* out = (float*)d_out;

    cudaFuncSetAttribute(flash_kernel,
                         cudaFuncAttributeMaxDynamicSharedMemorySize, FL_BYTES);

    prep_x<<<512, 256>>>(x);                               // launch 1
    prep_w<<<512, 256>>>(qkv_w, proj_w);                   // launch 2
    mm_fp16<0><<<dim3(32, 18), 256>>>(qkv_b, nullptr);     // launch 3
    relpos_kernel<<<192, 256>>>(rpd, rph, rpw);            // launch 4 (ncu)
    flash_kernel<<<dim3(16, NHB), 256, FL_BYTES>>>();      // launch 5
    mm_fp16<1><<<dim3(32, 6), 256>>>(proj_b, out);         // launch 6
}